// round 3
// baseline (speedup 1.0000x reference)
#include <cuda_runtime.h>

#define NC 19
#define HWS (512*512)
#define NPIX (16*HWS)                 // 4,194,304 pixels
#define EPSF 1e-8f
#define THREADS 256
#define VEC 4
#define NBLOCKS (NPIX/(THREADS*VEC))  // 4096

__device__ float g_partial[NBLOCKS];
__device__ unsigned int g_count;      // zero-initialized; self-resetting

__global__ void __launch_bounds__(THREADS)
emloss_fused(const float* __restrict__ logits,
             const int*   __restrict__ targets,
             const float* __restrict__ cm,
             float* __restrict__ pred_out,
             float* __restrict__ out_scalar)
{
    __shared__ float s_ncm[NC*NC];
    __shared__ float s_log[NC*NC];

    const int g  = blockIdx.x * THREADS + threadIdx.x;   // pixel-group index
    const int p0 = g * VEC;
    const int b  = p0 / HWS;                             // all 4 pixels in same image (HWS % 4 == 0)
    const int hw = p0 - b * HWS;
    const float4* lbase = (const float4*)(logits + (size_t)b * NC * HWS + hw);
    float4* pbase       = (float4*)(pred_out + (size_t)b * NC * HWS + hw);

    // Issue all 19 LDG.128 up front (MLP=19), plus targets
    float4 x[NC];
    #pragma unroll
    for (int c = 0; c < NC; c++)
        x[c] = __ldg(lbase + (size_t)c * (HWS / 4));
    const int4 t4 = *(const int4*)(targets + p0);

    // Recompute confusion-softmax tables per block — hides under load latency
    if (threadIdx.x < NC) {
        const int r = threadIdx.x;
        float row[NC];
        float m = -1e30f;
        #pragma unroll
        for (int j = 0; j < NC; j++) { row[j] = cm[r*NC + j]; m = fmaxf(m, row[j]); }
        float s = 0.f;
        #pragma unroll
        for (int j = 0; j < NC; j++) { row[j] = expf(row[j] - m); s += row[j]; }
        const float inv = 1.f / s;
        #pragma unroll
        for (int j = 0; j < NC; j++) {
            float v = row[j] * inv;
            s_ncm[r*NC + j] = v;
            s_log[r*NC + j] = logf(v + EPSF);
        }
    }
    __syncthreads();

    // Stable softmax over classes, 4 lanes at once
    float4 m4 = x[0];
    #pragma unroll
    for (int c = 1; c < NC; c++) {
        m4.x = fmaxf(m4.x, x[c].x); m4.y = fmaxf(m4.y, x[c].y);
        m4.z = fmaxf(m4.z, x[c].z); m4.w = fmaxf(m4.w, x[c].w);
    }
    float4 s4 = make_float4(0.f, 0.f, 0.f, 0.f);
    #pragma unroll
    for (int c = 0; c < NC; c++) {
        x[c].x = __expf(x[c].x - m4.x); s4.x += x[c].x;
        x[c].y = __expf(x[c].y - m4.y); s4.y += x[c].y;
        x[c].z = __expf(x[c].z - m4.z); s4.z += x[c].z;
        x[c].w = __expf(x[c].w - m4.w); s4.w += x[c].w;
    }
    const float4 inv4 = make_float4(1.f/s4.x, 1.f/s4.y, 1.f/s4.z, 1.f/s4.w);

    // Single pass: store pred, accumulate ns = sum w*p and A = sum w*p*(logw + log(p+eps))
    float4 ns = make_float4(0.f, 0.f, 0.f, 0.f);
    float4 A  = make_float4(0.f, 0.f, 0.f, 0.f);
    #pragma unroll
    for (int c = 0; c < NC; c++) {
        float4 pv;
        pv.x = x[c].x * inv4.x; pv.y = x[c].y * inv4.y;
        pv.z = x[c].z * inv4.z; pv.w = x[c].w * inv4.w;
        pbase[(size_t)c * (HWS / 4)] = pv;

        const float wx = s_ncm[c*NC + t4.x], lx = s_log[c*NC + t4.x];
        const float wy = s_ncm[c*NC + t4.y], ly = s_log[c*NC + t4.y];
        const float wz = s_ncm[c*NC + t4.z], lz = s_log[c*NC + t4.z];
        const float ww = s_ncm[c*NC + t4.w], lw = s_log[c*NC + t4.w];

        float ex = wx * pv.x, ey = wy * pv.y, ez = wz * pv.z, ew = ww * pv.w;
        ns.x += ex; ns.y += ey; ns.z += ez; ns.w += ew;
        A.x += ex * (lx + __logf(pv.x + EPSF));
        A.y += ey * (ly + __logf(pv.y + EPSF));
        A.z += ez * (lz + __logf(pv.z + EPSF));
        A.w += ew * (lw + __logf(pv.w + EPSF));
    }
    float loss = A.x / ns.x + A.y / ns.y + A.z / ns.z + A.w / ns.w;

    // Deterministic block reduction
    #pragma unroll
    for (int off = 16; off > 0; off >>= 1)
        loss += __shfl_down_sync(0xffffffffu, loss, off);

    __shared__ float s_red[THREADS/32];
    __shared__ bool  s_last;
    if ((threadIdx.x & 31) == 0) s_red[threadIdx.x >> 5] = loss;
    __syncthreads();
    if (threadIdx.x < (THREADS/32)) {
        float v = s_red[threadIdx.x];
        #pragma unroll
        for (int off = (THREADS/64); off > 0; off >>= 1)
            v += __shfl_down_sync(0xffu, v, off);
        if (threadIdx.x == 0) {
            g_partial[blockIdx.x] = v;
            __threadfence();
            unsigned int prev = atomicAdd(&g_count, 1u);
            s_last = (prev == NBLOCKS - 1);
        }
    }
    __syncthreads();

    // Last block does the deterministic final reduction
    if (s_last) {
        float s = 0.f;
        for (int i = threadIdx.x; i < NBLOCKS; i += THREADS)
            s += __ldcg(&g_partial[i]);                  // fixed order per thread
        #pragma unroll
        for (int off = 16; off > 0; off >>= 1)
            s += __shfl_down_sync(0xffffffffu, s, off);
        if ((threadIdx.x & 31) == 0) s_red[threadIdx.x >> 5] = s;
        __syncthreads();
        if (threadIdx.x < (THREADS/32)) {
            float v = s_red[threadIdx.x];
            #pragma unroll
            for (int off = (THREADS/64); off > 0; off >>= 1)
                v += __shfl_down_sync(0xffu, v, off);
            if (threadIdx.x == 0) {
                out_scalar[0] = -v / (float)NPIX;
                g_count = 0;                             // reset for next graph replay
            }
        }
    }
}

extern "C" void kernel_launch(void* const* d_in, const int* in_sizes, int n_in,
                              void* d_out, int out_size) {
    const float* logits  = (const float*)d_in[0];
    const int*   targets = (const int*)d_in[1];
    const float* cm      = (const float*)d_in[2];
    float* out = (float*)d_out;

    emloss_fused<<<NBLOCKS, THREADS>>>(logits, targets, cm, out, out + (out_size - 1));
}